// round 15
// baseline (speedup 1.0000x reference)
#include <cuda_runtime.h>
#include <cuda_fp16.h>
#include <cstdint>

#define NTOK 49
#define MPAD 64
#define DIM 128
#define HEADS 4
#define HD 32
#define NWIN 64
#define NBLK 4096
#define NROWS (NBLK * NTOK)          // 200704

// half2-unit strides (conflict-free: +4 pad => ldmatrix phases hit distinct banks)
#define SH 68    // q/k/x/w/o tiles: row = 64 data half2 + 4 pad  (136 halves)
#define SVT 36   // V^T tile: row = 32 data half2 + 4 pad         (72 halves)

// ---------------- global scratch (allocation-free) ----------------
__device__ __half g_q[NROWS * DIM];
__device__ __half g_k[NROWS * DIM];
__device__ __half g_v[NROWS * DIM];
// fused (relbias + mask) in mma C-fragment layout: [win][h][mg][rs][nt][lane]
__device__ float2 g_biasF[NWIN * HEADS * 4 * 2 * 8 * 32];

__global__ void biasfrag_kernel(const float* __restrict__ bias_table,
                                const int* __restrict__ rel_index,
                                const float* __restrict__ mask)
{
    int idx = blockIdx.x * 256 + threadIdx.x;
    int lane = idx & 31;
    int nt   = (idx >> 5) & 7;
    int rs   = (idx >> 8) & 1;
    int mg   = (idx >> 9) & 3;
    int h    = (idx >> 11) & 3;
    int win  = idx >> 13;
    int g = lane >> 2, tg = lane & 3;
    int r = mg * 16 + rs * 8 + g;
    int c0 = nt * 8 + 2 * tg;

    float2 v;
    if (c0 >= NTOK)      v.x = -1e30f;
    else if (r >= NTOK)  v.x = 0.f;
    else v.x = bias_table[rel_index[r * NTOK + c0] * HEADS + h]
             + mask[(win * NTOK + r) * NTOK + c0];
    int c1 = c0 + 1;
    if (c1 >= NTOK)      v.y = -1e30f;
    else if (r >= NTOK)  v.y = 0.f;
    else v.y = bias_table[rel_index[r * NTOK + c1] * HEADS + h]
             + mask[(win * NTOK + r) * NTOK + c1];

    g_biasF[idx] = v;
}

__device__ __forceinline__ uint32_t h2pack(float x, float y) {
    __half2 h = __floats2half2_rn(x, y);
    return *reinterpret_cast<uint32_t*>(&h);
}

__device__ __forceinline__ uint32_t smaddr(const void* p) {
    return (uint32_t)__cvta_generic_to_shared(p);
}

// load 4 8x8 b16 matrices: one warp-wide LDSM
__device__ __forceinline__ void ldsm4(uint32_t r[4], uint32_t a) {
    asm volatile("ldmatrix.sync.aligned.m8n8.x4.shared.b16 {%0,%1,%2,%3}, [%4];"
                 : "=r"(r[0]), "=r"(r[1]), "=r"(r[2]), "=r"(r[3]) : "r"(a));
}

// fp16 mma: D(16x8,f32) += A(16x16,f16) x B(16x8,f16 col-major)
__device__ __forceinline__ void mma16(float c[4], const uint32_t a[4], const uint32_t b[2]) {
    asm volatile(
        "mma.sync.aligned.m16n8k16.row.col.f32.f16.f16.f32 "
        "{%0,%1,%2,%3}, {%4,%5,%6,%7}, {%8,%9}, {%0,%1,%2,%3};\n"
        : "+f"(c[0]), "+f"(c[1]), "+f"(c[2]), "+f"(c[3])
        : "r"(a[0]), "r"(a[1]), "r"(a[2]), "r"(a[3]), "r"(b[0]), "r"(b[1]));
}

// A-tile ldmatrix lane offset (halves): 16 rows x 16 cols tile
// lanes 0-15 -> rows 0..15 col 0; lanes 16-31 -> rows 0..15 col 8
__device__ __forceinline__ int ldsmA_off(int lane, int rowStrideH) {
    return (lane & 15) * rowStrideH + (lane >> 4) * 8;
}
// B-tile ldmatrix lane offset (halves): 16 n-rows x 16 k-cols
// lanes 0-7: n 0..7 k0; 8-15: n 0..7 k8; 16-23: n 8..15 k0; 24-31: n 8..15 k8
__device__ __forceinline__ int ldsmB_off(int lane, int rowStrideH) {
    int row = (lane & 7) | ((lane >> 4) << 3);
    int col = ((lane >> 3) & 1) * 8;
    return row * rowStrideH + col;
}

// =====================================================================
// Projection GEMM (Q/K/V): fp32 in, fp16 mma, fp16 out.
// M-tile 128. X and FULL W in smem as fp16. LDSM fragment loads. 2 CTAs/SM.
// =====================================================================
__global__ __launch_bounds__(256, 2)
void proj_kernel(const float* __restrict__ X0, const float* __restrict__ X1,
                 const float* __restrict__ X2,
                 const float* __restrict__ W0_, const float* __restrict__ W1_,
                 const float* __restrict__ W2_,
                 const float* __restrict__ B0_, const float* __restrict__ B1_,
                 const float* __restrict__ B2_,
                 __half* __restrict__ O0_, __half* __restrict__ O1_,
                 __half* __restrict__ O2_,
                 float a0, float a1, float a2)
{
    extern __shared__ uint32_t smu[];
    uint32_t* sX = smu;              // 128 x SH half2
    uint32_t* sW = smu + 128 * SH;   // 128 x SH half2

    const float* X; const float* W; const float* Bb; __half* O; float alpha;
    if (blockIdx.y == 0)      { X = X0; W = W0_; Bb = B0_; O = O0_; alpha = a0; }
    else if (blockIdx.y == 1) { X = X1; W = W1_; Bb = B1_; O = O1_; alpha = a1; }
    else                      { X = X2; W = W2_; Bb = B2_; O = O2_; alpha = a2; }

    const int tid  = threadIdx.x;
    const int warp = tid >> 5, lane = tid & 31;
    const int g = lane >> 2, tg = lane & 3;
    const int mBase = blockIdx.x * 128;

    // ---- stage X and W as fp16 ----
    const float4* gX = reinterpret_cast<const float4*>(X + mBase * DIM);
    const float4* gW = reinterpret_cast<const float4*>(W);
    #pragma unroll
    for (int t = 0; t < 16; t++) {
        int f = t * 256 + tid;
        int r = f >> 5, c4 = f & 31;
        float4 v = gX[f];
        uint2 u = make_uint2(h2pack(v.x, v.y), h2pack(v.z, v.w));
        *reinterpret_cast<uint2*>(&sX[r * SH + 2 * c4]) = u;
        float4 w = gW[f];
        uint2 uw = make_uint2(h2pack(w.x, w.y), h2pack(w.z, w.w));
        *reinterpret_cast<uint2*>(&sW[r * SH + 2 * c4]) = uw;
    }
    __syncthreads();

    const int wm = warp & 3;     // 4 m-chunks of 32 rows
    const int wn = warp >> 2;    // 2 n-chunks of 64 cols
    float acc[2][8][4];
    #pragma unroll
    for (int mt = 0; mt < 2; mt++)
        #pragma unroll
        for (int nt = 0; nt < 8; nt++)
            #pragma unroll
            for (int j = 0; j < 4; j++) acc[mt][nt][j] = 0.f;

    // LDSM base addresses (bytes)
    uint32_t aB[2], bB[4];
    #pragma unroll
    for (int mt = 0; mt < 2; mt++)
        aB[mt] = smaddr(sX) + 2 * ((wm * 32 + mt * 16) * 136 + ldsmA_off(lane, 136));
    #pragma unroll
    for (int p = 0; p < 4; p++)
        bB[p] = smaddr(sW) + 2 * ((wn * 64 + p * 16) * 136 + ldsmB_off(lane, 136));

    #pragma unroll
    for (int kk = 0; kk < 8; kk++) {
        uint32_t a[2][4];
        ldsm4(a[0], aB[0] + kk * 32);
        ldsm4(a[1], aB[1] + kk * 32);
        #pragma unroll
        for (int p = 0; p < 4; p++) {
            uint32_t bb[4];
            ldsm4(bb, bB[p] + kk * 32);
            mma16(acc[0][2 * p],     a[0], bb);
            mma16(acc[1][2 * p],     a[1], bb);
            mma16(acc[0][2 * p + 1], a[0], bb + 2);
            mma16(acc[1][2 * p + 1], a[1], bb + 2);
        }
    }

    // ---- epilogue: bias, alpha, fp16 stores ----
    #pragma unroll
    for (int mt = 0; mt < 2; mt++) {
        const int r0 = mBase + wm * 32 + mt * 16 + g;
        #pragma unroll
        for (int nt = 0; nt < 8; nt++) {
            const int c = wn * 64 + nt * 8 + 2 * tg;
            const float b0 = Bb[c], b1 = Bb[c + 1];
            *reinterpret_cast<uint32_t*>(O + r0 * DIM + c) =
                h2pack((acc[mt][nt][0] + b0) * alpha, (acc[mt][nt][1] + b1) * alpha);
            *reinterpret_cast<uint32_t*>(O + (r0 + 8) * DIM + c) =
                h2pack((acc[mt][nt][2] + b0) * alpha, (acc[mt][nt][3] + b1) * alpha);
        }
    }
}

// =====================================================================
// Fused attention + output projection, all-fp16 mma + LDSM.
// smem: q[64xSH] k[64xSH] vT[128xSVT] = 52KB. O overlays q; Wp overlays k+vT.
// =====================================================================
__global__ __launch_bounds__(256, 2)
void attn_proj_kernel(const __half* __restrict__ gq, const __half* __restrict__ gk,
                      const __half* __restrict__ gv, const float* __restrict__ Wp,
                      const float* __restrict__ bp, float* __restrict__ out)
{
    extern __shared__ uint32_t smu[];
    uint32_t* sQ  = smu;                   // 64 x SH half2  (later: O fp16)
    uint32_t* sK  = smu + MPAD * SH;       // 64 x SH half2  (later: Wp)
    uint32_t* sVT = sK + MPAD * SH;        // 128 x SVT half2
    unsigned short* sVTus = reinterpret_cast<unsigned short*>(sVT);

    const int tid = threadIdx.x;
    const int warp = tid >> 5, lane = tid & 31;
    const int g = lane >> 2, tg = lane & 3;
    const int b = blockIdx.x;
    const int base = b * NTOK * DIM;

    // ---- phase 0: zero vT fully + q/k pad rows (tokens 49..63) ----
    {
        uint4 z = make_uint4(0, 0, 0, 0);
        uint4* zv = reinterpret_cast<uint4*>(sVT);
        #pragma unroll
        for (int t = 0; t < 5; t++) {
            int i = t * 256 + tid;
            if (i < 128 * SVT / 4) zv[i] = z;       // 1152 uint4
        }
        if (tid < 255) {                            // 15 rows x 17 uint4
            int row = 49 + tid / 17, c = tid % 17;
            reinterpret_cast<uint4*>(sQ)[row * 17 + c] = z;
            reinterpret_cast<uint4*>(sK)[row * 17 + c] = z;
        }
    }
    __syncthreads();

    // ---- phase 1: stage q/k (raw copy) + v (transpose) ----
    {
        const uint4* Gq = reinterpret_cast<const uint4*>(gq + base);
        const uint4* Gk = reinterpret_cast<const uint4*>(gk + base);
        const uint4* Gv = reinterpret_cast<const uint4*>(gv + base);
        uint4 rq[3], rk[3], rv[3], tq, tk, tv;
        const bool hasTail = tid < 16;
        if (hasTail) { tq = Gq[768 + tid]; tk = Gk[768 + tid]; tv = Gv[768 + tid]; }
        #pragma unroll
        for (int t = 0; t < 3; t++) rq[t] = Gq[t * 256 + tid];
        #pragma unroll
        for (int t = 0; t < 3; t++) rk[t] = Gk[t * 256 + tid];
        #pragma unroll
        for (int t = 0; t < 3; t++) rv[t] = Gv[t * 256 + tid];

        uint4* q4 = reinterpret_cast<uint4*>(sQ);
        uint4* k4 = reinterpret_cast<uint4*>(sK);
        #pragma unroll
        for (int t = 0; t < 3; t++) {
            int f = t * 256 + tid;
            int r = f >> 4, c16 = f & 15;
            q4[r * 17 + c16] = rq[t];
            k4[r * 17 + c16] = rk[t];
            uint32_t w[4] = { rv[t].x, rv[t].y, rv[t].z, rv[t].w };
            int d0 = c16 * 8;
            #pragma unroll
            for (int j = 0; j < 4; j++) {
                sVTus[(d0 + 2 * j) * (2 * SVT) + r]     = (unsigned short)(w[j] & 0xffff);
                sVTus[(d0 + 2 * j + 1) * (2 * SVT) + r] = (unsigned short)(w[j] >> 16);
            }
        }
        if (hasTail) {
            int f = 768 + tid;
            int r = f >> 4, c16 = f & 15;       // row 48
            q4[r * 17 + c16] = tq;
            k4[r * 17 + c16] = tk;
            uint32_t w[4] = { tv.x, tv.y, tv.z, tv.w };
            int d0 = c16 * 8;
            #pragma unroll
            for (int j = 0; j < 4; j++) {
                sVTus[(d0 + 2 * j) * (2 * SVT) + r]     = (unsigned short)(w[j] & 0xffff);
                sVTus[(d0 + 2 * j + 1) * (2 * SVT) + r] = (unsigned short)(w[j] >> 16);
            }
        }
    }
    __syncthreads();

    const float2* bwin = g_biasF + (size_t)(b & (NWIN - 1)) * (HEADS * 4 * 2 * 8 * 32);

    float accO[2][4][4];
    #pragma unroll
    for (int task = 0; task < 2; task++)
        #pragma unroll
        for (int nt = 0; nt < 4; nt++)
            #pragma unroll
            for (int j = 0; j < 4; j++) accO[task][nt][j] = 0.f;

    const int laneAoff = ldsmA_off(lane, 136);
    const int laneBoff = ldsmB_off(lane, 136);
    const int laneVoff = ldsmB_off(lane, 72);

    #pragma unroll
    for (int task = 0; task < 2; task++) {
        const int rg = task * 8 + warp;        // 0..15
        const int h  = rg >> 2;
        const int mg = rg & 3;
        const int mB = mg * 16;

        // ---- S = q_h @ k_h^T: 16x64, k=32 (2 mma k-steps) ----
        float accS[8][4];
        #pragma unroll
        for (int nt = 0; nt < 8; nt++)
            #pragma unroll
            for (int j = 0; j < 4; j++) accS[nt][j] = 0.f;

        const uint32_t aS = smaddr(sQ) + 2 * (mB * 136 + h * 32 + laneAoff);
        #pragma unroll
        for (int kk = 0; kk < 2; kk++) {
            uint32_t a[4];
            ldsm4(a, aS + kk * 32);
            #pragma unroll
            for (int p = 0; p < 4; p++) {
                uint32_t bb[4];
                ldsm4(bb, smaddr(sK) + 2 * (p * 16 * 136 + h * 32 + laneBoff) + kk * 32);
                mma16(accS[2 * p],     a, bb);
                mma16(accS[2 * p + 1], a, bb + 2);
            }
        }

        // ---- fused bias fragments (16 coalesced LDG.64) ----
        const float2* bfp = bwin + ((h * 4 + mg) * 2 * 8) * 32 + lane;
        float2 bR[2][8];
        #pragma unroll
        for (int rs = 0; rs < 2; rs++)
            #pragma unroll
            for (int nt = 0; nt < 8; nt++)
                bR[rs][nt] = bfp[(rs * 8 + nt) * 32];

        // ---- bias + softmax in-register; accS becomes P ----
        #pragma unroll
        for (int rs = 0; rs < 2; rs++) {
            float lv[16];
            #pragma unroll
            for (int nt = 0; nt < 8; nt++) {
                lv[nt * 2 + 0] = accS[nt][rs * 2 + 0] + bR[rs][nt].x;
                lv[nt * 2 + 1] = accS[nt][rs * 2 + 1] + bR[rs][nt].y;
            }
            float m = lv[0];
            #pragma unroll
            for (int i = 1; i < 16; i++) m = fmaxf(m, lv[i]);
            m = fmaxf(m, __shfl_xor_sync(0xffffffffu, m, 1));
            m = fmaxf(m, __shfl_xor_sync(0xffffffffu, m, 2));
            float s = 0.f;
            #pragma unroll
            for (int i = 0; i < 16; i++) { lv[i] = __expf(lv[i] - m); s += lv[i]; }
            s += __shfl_xor_sync(0xffffffffu, s, 1);
            s += __shfl_xor_sync(0xffffffffu, s, 2);
            const float inv = 1.f / s;
            #pragma unroll
            for (int nt = 0; nt < 8; nt++) {
                accS[nt][rs * 2 + 0] = lv[nt * 2 + 0] * inv;
                accS[nt][rs * 2 + 1] = lv[nt * 2 + 1] * inv;
            }
        }

        // ---- O = P @ V_h: A-frags by packing C-frags; B via LDSM on vT ----
        #pragma unroll
        for (int kk = 0; kk < 4; kk++) {       // 64 tokens = 4 k16 steps
            uint32_t a[4];
            a[0] = h2pack(accS[2 * kk][0],     accS[2 * kk][1]);
            a[1] = h2pack(accS[2 * kk][2],     accS[2 * kk][3]);
            a[2] = h2pack(accS[2 * kk + 1][0], accS[2 * kk + 1][1]);
            a[3] = h2pack(accS[2 * kk + 1][2], accS[2 * kk + 1][3]);
            #pragma unroll
            for (int p = 0; p < 2; p++) {
                uint32_t bb[4];
                ldsm4(bb, smaddr(sVT) + 2 * ((h * HD + p * 16) * 72 + laneVoff) + kk * 32);
                mma16(accO[task][2 * p],     a, bb);
                mma16(accO[task][2 * p + 1], a, bb + 2);
            }
        }
    }
    __syncthreads();   // done reading q/k/vT

    // ---- O tile (fp16) into sQ region; whole Wp (fp16) into sK.. ----
    #pragma unroll
    for (int task = 0; task < 2; task++) {
        const int rg = task * 8 + warp;
        const int h  = rg >> 2;
        const int mB = (rg & 3) * 16;
        #pragma unroll
        for (int nt = 0; nt < 4; nt++) {
            const int c2 = h * 16 + nt * 4 + tg;   // half2 col index
            sQ[(mB + g) * SH + c2]     = h2pack(accO[task][nt][0], accO[task][nt][1]);
            sQ[(mB + 8 + g) * SH + c2] = h2pack(accO[task][nt][2], accO[task][nt][3]);
        }
    }
    uint32_t* sWp = sK;    // 128 x SH half2 = 8704 words (fits in sK+sVT = 8960)
    {
        const float4* gW = reinterpret_cast<const float4*>(Wp);
        #pragma unroll
        for (int t = 0; t < 16; t++) {
            int f = t * 256 + tid;
            int r = f >> 5, c4 = f & 31;
            float4 w = gW[f];
            uint2 uw = make_uint2(h2pack(w.x, w.y), h2pack(w.z, w.w));
            *reinterpret_cast<uint2*>(&sWp[r * SH + 2 * c4]) = uw;
        }
    }
    __syncthreads();

    // ---- out[64,128] = O @ Wp^T + bp ----
    const int wm = warp & 3;     // rows 16*wm
    const int wn = warp >> 2;    // cols 64*wn
    float acc2[8][4];
    #pragma unroll
    for (int nt = 0; nt < 8; nt++)
        #pragma unroll
        for (int j = 0; j < 4; j++) acc2[nt][j] = 0.f;

    const uint32_t aO = smaddr(sQ) + 2 * (wm * 16 * 136 + laneAoff);
    uint32_t bO[4];
    #pragma unroll
    for (int p = 0; p < 4; p++)
        bO[p] = smaddr(sWp) + 2 * ((wn * 64 + p * 16) * 136 + laneBoff);

    #pragma unroll
    for (int kk = 0; kk < 8; kk++) {
        uint32_t a[4];
        ldsm4(a, aO + kk * 32);
        #pragma unroll
        for (int p = 0; p < 4; p++) {
            uint32_t bb[4];
            ldsm4(bb, bO[p] + kk * 32);
            mma16(acc2[2 * p],     a, bb);
            mma16(acc2[2 * p + 1], a, bb + 2);
        }
    }

    const int r0 = wm * 16 + g, r1 = r0 + 8;
    #pragma unroll
    for (int nt = 0; nt < 8; nt++) {
        const int c = wn * 64 + nt * 8 + 2 * tg;
        const float b0 = bp[c], b1 = bp[c + 1];
        if (r0 < NTOK)
            *reinterpret_cast<float2*>(out + base + r0 * DIM + c) =
                make_float2(acc2[nt][0] + b0, acc2[nt][1] + b1);
        if (r1 < NTOK)
            *reinterpret_cast<float2*>(out + base + r1 * DIM + c) =
                make_float2(acc2[nt][2] + b0, acc2[nt][3] + b1);
    }
}

#define PROJ_SMEM (2 * 128 * SH * 4)                       // 69632 B
#define ATTN_SMEM ((2 * MPAD * SH + 128 * SVT) * 4)        // 53248 B
#define QSCALE 0.17677669529663687f

extern "C" void kernel_launch(void* const* d_in, const int* in_sizes, int n_in,
                              void* d_out, int out_size)
{
    const float* query      = (const float*)d_in[0];
    const float* key        = (const float*)d_in[1];
    const float* value      = (const float*)d_in[2];
    const float* Wq         = (const float*)d_in[3];
    const float* bq         = (const float*)d_in[4];
    const float* Wk         = (const float*)d_in[5];
    const float* bk         = (const float*)d_in[6];
    const float* Wv         = (const float*)d_in[7];
    const float* bv         = (const float*)d_in[8];
    const float* bias_table = (const float*)d_in[9];
    const float* Wp         = (const float*)d_in[10];
    const float* bp         = (const float*)d_in[11];
    const float* mask       = (const float*)d_in[12];
    const int*   rel_index  = (const int*)d_in[13];
    float* out = (float*)d_out;

    __half* q = nullptr; __half* k = nullptr; __half* v = nullptr;
    cudaGetSymbolAddress((void**)&q,  g_q);
    cudaGetSymbolAddress((void**)&k,  g_k);
    cudaGetSymbolAddress((void**)&v,  g_v);

    cudaFuncSetAttribute(proj_kernel,
                         cudaFuncAttributeMaxDynamicSharedMemorySize, PROJ_SMEM);
    cudaFuncSetAttribute(attn_proj_kernel,
                         cudaFuncAttributeMaxDynamicSharedMemorySize, ATTN_SMEM);

    biasfrag_kernel<<<(NWIN * HEADS * 4 * 2 * 8 * 32) / 256, 256>>>(
        bias_table, rel_index, mask);

    proj_kernel<<<dim3(NROWS / 128, 3), 256, PROJ_SMEM>>>(
        query, key, value, Wq, Wk, Wv, bq, bk, bv, q, k, v,
        QSCALE, 1.f, 1.f);

    attn_proj_kernel<<<NBLK, 256, ATTN_SMEM>>>(q, k, v, Wp, bp, out);
}

// round 17
// speedup vs baseline: 1.0516x; 1.0516x over previous
#include <cuda_runtime.h>
#include <cuda_fp16.h>
#include <cstdint>

#define NTOK 49
#define MPAD 64
#define DIM 128
#define HEADS 4
#define HD 32
#define NWIN 64
#define NBLK 4096
#define NROWS (NBLK * NTOK)

// half2-unit stride: 64 data half2 + 4 pad (136 halves, 272 B/row)
#define SH 68
#define W16N (128 * SH)          // uint32 per padded fp16 weight

// ---------------- global scratch (allocation-free) ----------------
__device__ uint32_t g_w16[4 * W16N];   // Wq,Wk,Wv,Wp as padded fp16 half2 rows
// fused (relbias + mask) in mma C-fragment layout: [win][h][mg][rs][nt][lane]
__device__ float2 g_biasF[NWIN * HEADS * 4 * 2 * 8 * 32];

__device__ __forceinline__ uint32_t h2pack(float x, float y) {
    __half2 h = __floats2half2_rn(x, y);
    return *reinterpret_cast<uint32_t*>(&h);
}

__global__ void biasfrag_kernel(const float* __restrict__ bias_table,
                                const int* __restrict__ rel_index,
                                const float* __restrict__ mask)
{
    int idx = blockIdx.x * 256 + threadIdx.x;
    int lane = idx & 31;
    int nt   = (idx >> 5) & 7;
    int rs   = (idx >> 8) & 1;
    int mg   = (idx >> 9) & 3;
    int h    = (idx >> 11) & 3;
    int win  = idx >> 13;
    int g = lane >> 2, tg = lane & 3;
    int r = mg * 16 + rs * 8 + g;
    int c0 = nt * 8 + 2 * tg;

    float2 v;
    if (c0 >= NTOK)      v.x = -1e30f;
    else if (r >= NTOK)  v.x = 0.f;
    else v.x = bias_table[rel_index[r * NTOK + c0] * HEADS + h]
             + mask[(win * NTOK + r) * NTOK + c0];
    int c1 = c0 + 1;
    if (c1 >= NTOK)      v.y = -1e30f;
    else if (r >= NTOK)  v.y = 0.f;
    else v.y = bias_table[rel_index[r * NTOK + c1] * HEADS + h]
             + mask[(win * NTOK + r) * NTOK + c1];

    g_biasF[idx] = v;
}

// convert the 4 weight matrices to padded fp16 layout (ready for raw smem copy)
__global__ void w16_kernel(const float* __restrict__ Wq, const float* __restrict__ Wk,
                           const float* __restrict__ Wv, const float* __restrict__ Wp)
{
    int idx = blockIdx.x * 256 + threadIdx.x;   // 4*128*64 = 32768 exact
    int c2 = idx & 63;
    int r  = (idx >> 6) & 127;
    int w  = idx >> 13;
    const float* W = (w == 0) ? Wq : (w == 1) ? Wk : (w == 2) ? Wv : Wp;
    float2 v = *reinterpret_cast<const float2*>(W + r * DIM + 2 * c2);
    g_w16[w * W16N + r * SH + c2] = h2pack(v.x, v.y);
}

__device__ __forceinline__ uint32_t smaddr(const void* p) {
    return (uint32_t)__cvta_generic_to_shared(p);
}
__device__ __forceinline__ void ldsm4(uint32_t r[4], uint32_t a) {
    asm volatile("ldmatrix.sync.aligned.m8n8.x4.shared.b16 {%0,%1,%2,%3}, [%4];"
                 : "=r"(r[0]), "=r"(r[1]), "=r"(r[2]), "=r"(r[3]) : "r"(a));
}
__device__ __forceinline__ void ldsm4t(uint32_t r[4], uint32_t a) {
    asm volatile("ldmatrix.sync.aligned.m8n8.x4.trans.shared.b16 {%0,%1,%2,%3}, [%4];"
                 : "=r"(r[0]), "=r"(r[1]), "=r"(r[2]), "=r"(r[3]) : "r"(a));
}
__device__ __forceinline__ void mma16(float c[4], const uint32_t a[4], const uint32_t b[2]) {
    asm volatile(
        "mma.sync.aligned.m16n8k16.row.col.f32.f16.f16.f32 "
        "{%0,%1,%2,%3}, {%4,%5,%6,%7}, {%8,%9}, {%0,%1,%2,%3};\n"
        : "+f"(c[0]), "+f"(c[1]), "+f"(c[2]), "+f"(c[3])
        : "r"(a[0]), "r"(a[1]), "r"(a[2]), "r"(a[3]), "r"(b[0]), "r"(b[1]));
}
__device__ __forceinline__ int ldsmA_off(int lane) {
    return (lane & 15) * 136 + (lane >> 4) * 8;
}
__device__ __forceinline__ int ldsmB_off(int lane) {
    int row = (lane & 7) | ((lane >> 4) << 3);
    int col = ((lane >> 3) & 1) * 8;
    return row * 136 + col;
}

// stage 49x128 fp32 -> fp16 smem tile; rows 49..63 zeroed
__device__ __forceinline__ void stage_X(uint32_t* sX, const float* __restrict__ gX, int tid) {
    #pragma unroll
    for (int t = 0; t < 7; t++) {
        int f = t * 256 + tid;
        if (f < NTOK * 32) {
            int r = f >> 5, c4 = f & 31;
            float4 v = reinterpret_cast<const float4*>(gX)[f];
            *reinterpret_cast<uint2*>(&sX[r * SH + 2 * c4]) =
                make_uint2(h2pack(v.x, v.y), h2pack(v.z, v.w));
        }
    }
    if (tid < 255) {
        int row = 49 + tid / 17, c = tid % 17;
        reinterpret_cast<uint4*>(sX)[row * 17 + c] = make_uint4(0, 0, 0, 0);
    }
}

// raw copy of one padded fp16 weight (8704 uint32 = 2176 uint4) into smem
__device__ __forceinline__ void copy_W(uint32_t* sW, const uint32_t* __restrict__ gw, int tid) {
    const uint4* src = reinterpret_cast<const uint4*>(gw);
    uint4* dst = reinterpret_cast<uint4*>(sW);
    #pragma unroll
    for (int t = 0; t < 9; t++) {
        int i = t * 256 + tid;
        if (i < 2176) dst[i] = src[i];
    }
}

// C[64,128] = A(sX fp16) @ W^T + bias, (*alpha), fp16 -> dst tile
__device__ __forceinline__ void proj_gemm(const uint32_t* sX, const uint32_t* sW,
                                          uint32_t* dst, const float* __restrict__ Bb,
                                          float alpha, int warp, int lane)
{
    const int g = lane >> 2, tg = lane & 3;
    const int wm = warp & 3, wn = warp >> 2;
    float acc[8][4];
    #pragma unroll
    for (int nt = 0; nt < 8; nt++)
        #pragma unroll
        for (int j = 0; j < 4; j++) acc[nt][j] = 0.f;

    const uint32_t aB = smaddr(sX) + 2 * (wm * 16 * 136 + ldsmA_off(lane));
    uint32_t bB[4];
    #pragma unroll
    for (int p = 0; p < 4; p++)
        bB[p] = smaddr(sW) + 2 * ((wn * 64 + p * 16) * 136 + ldsmB_off(lane));

    #pragma unroll
    for (int kk = 0; kk < 8; kk++) {
        uint32_t a[4];
        ldsm4(a, aB + kk * 32);
        #pragma unroll
        for (int p = 0; p < 4; p++) {
            uint32_t bb[4];
            ldsm4(bb, bB[p] + kk * 32);
            mma16(acc[2 * p],     a, bb);
            mma16(acc[2 * p + 1], a, bb + 2);
        }
    }

    #pragma unroll
    for (int nt = 0; nt < 8; nt++) {
        const int c = wn * 64 + nt * 8 + 2 * tg;
        const float b0 = Bb[c], b1 = Bb[c + 1];
        const int c2 = wn * 32 + nt * 4 + tg;
        dst[(wm * 16 + g) * SH + c2] =
            h2pack((acc[nt][0] + b0) * alpha, (acc[nt][1] + b1) * alpha);
        dst[(wm * 16 + 8 + g) * SH + c2] =
            h2pack((acc[nt][2] + b0) * alpha, (acc[nt][3] + b1) * alpha);
    }
}

#define QSCALE 0.17677669529663687f

// =====================================================================
// Fully fused: per-window projections + attention + output projection.
// smem: sX(64) sW(128) sQt(64) sKt(64) sVt(64) rows x SH = 104448 B.
// 256 threads, 2 CTAs/SM.
// =====================================================================
__global__ __launch_bounds__(256, 2)
void swin_kernel(const float* __restrict__ query, const float* __restrict__ key,
                 const float* __restrict__ value,
                 const float* __restrict__ bq, const float* __restrict__ bk,
                 const float* __restrict__ bv, const float* __restrict__ bp,
                 float* __restrict__ out)
{
    extern __shared__ uint32_t smu[];
    uint32_t* sX  = smu;                  // X staging, later O tile
    uint32_t* sW  = smu + MPAD * SH;      // current weight (128 x SH)
    uint32_t* sQt = sW + 128 * SH;
    uint32_t* sKt = sQt + MPAD * SH;
    uint32_t* sVt = sKt + MPAD * SH;      // v row-major (token x dim)

    const int tid = threadIdx.x;
    const int warp = tid >> 5, lane = tid & 31;
    const int g = lane >> 2, tg = lane & 3;
    const int b = blockIdx.x;
    const int base = b * NTOK * DIM;

    // ---- q projection ----
    stage_X(sX, query + base, tid);
    copy_W(sW, g_w16 + 0 * W16N, tid);
    __syncthreads();
    proj_gemm(sX, sW, sQt, bq, QSCALE, warp, lane);
    __syncthreads();
    // ---- k projection ----
    stage_X(sX, key + base, tid);
    copy_W(sW, g_w16 + 1 * W16N, tid);
    __syncthreads();
    proj_gemm(sX, sW, sKt, bk, 1.f, warp, lane);
    __syncthreads();
    // ---- v projection ----
    stage_X(sX, value + base, tid);
    copy_W(sW, g_w16 + 2 * W16N, tid);
    __syncthreads();
    proj_gemm(sX, sW, sVt, bv, 1.f, warp, lane);
    __syncthreads();

    // ---- Wp copy issued now; overlaps attention compute ----
    copy_W(sW, g_w16 + 3 * W16N, tid);

    // ---- attention: 8 warps x 2 tasks = 16 (head, 16-row group) ----
    const float2* bwin = g_biasF + (size_t)(b & (NWIN - 1)) * (HEADS * 4 * 2 * 8 * 32);
    const int laneA = ldsmA_off(lane);
    const int laneB = ldsmB_off(lane);
    const int vrow = (lane & 7) | (((lane >> 3) & 1) << 3);
    const int vcol = (lane >> 4) * 8;

    float accO[2][4][4];
    #pragma unroll
    for (int task = 0; task < 2; task++)
        #pragma unroll
        for (int nt = 0; nt < 4; nt++)
            #pragma unroll
            for (int j = 0; j < 4; j++) accO[task][nt][j] = 0.f;

    #pragma unroll
    for (int task = 0; task < 2; task++) {
        const int rg = task * 8 + warp;
        const int h  = rg >> 2;
        const int mg = rg & 3;
        const int mB = mg * 16;

        float accS[8][4];
        #pragma unroll
        for (int nt = 0; nt < 8; nt++)
            #pragma unroll
            for (int j = 0; j < 4; j++) accS[nt][j] = 0.f;

        const uint32_t aS = smaddr(sQt) + 2 * (mB * 136 + h * 32 + laneA);
        #pragma unroll
        for (int kk = 0; kk < 2; kk++) {
            uint32_t a[4];
            ldsm4(a, aS + kk * 32);
            #pragma unroll
            for (int p = 0; p < 4; p++) {
                uint32_t bb[4];
                ldsm4(bb, smaddr(sKt) + 2 * (p * 16 * 136 + h * 32 + laneB) + kk * 32);
                mma16(accS[2 * p],     a, bb);
                mma16(accS[2 * p + 1], a, bb + 2);
            }
        }

        const float2* bfp = bwin + ((h * 4 + mg) * 2 * 8) * 32 + lane;
        float2 bR[2][8];
        #pragma unroll
        for (int rs = 0; rs < 2; rs++)
            #pragma unroll
            for (int nt = 0; nt < 8; nt++)
                bR[rs][nt] = bfp[(rs * 8 + nt) * 32];

        #pragma unroll
        for (int rs = 0; rs < 2; rs++) {
            float lv[16];
            #pragma unroll
            for (int nt = 0; nt < 8; nt++) {
                lv[nt * 2 + 0] = accS[nt][rs * 2 + 0] + bR[rs][nt].x;
                lv[nt * 2 + 1] = accS[nt][rs * 2 + 1] + bR[rs][nt].y;
            }
            float m = lv[0];
            #pragma unroll
            for (int i = 1; i < 16; i++) m = fmaxf(m, lv[i]);
            m = fmaxf(m, __shfl_xor_sync(0xffffffffu, m, 1));
            m = fmaxf(m, __shfl_xor_sync(0xffffffffu, m, 2));
            float s = 0.f;
            #pragma unroll
            for (int i = 0; i < 16; i++) { lv[i] = __expf(lv[i] - m); s += lv[i]; }
            s += __shfl_xor_sync(0xffffffffu, s, 1);
            s += __shfl_xor_sync(0xffffffffu, s, 2);
            const float inv = 1.f / s;
            #pragma unroll
            for (int nt = 0; nt < 8; nt++) {
                accS[nt][rs * 2 + 0] = lv[nt * 2 + 0] * inv;
                accS[nt][rs * 2 + 1] = lv[nt * 2 + 1] * inv;
            }
        }

        // O = P @ V_h: A by packing C-frags; B via ldmatrix.trans on row-major v
        #pragma unroll
        for (int kk = 0; kk < 4; kk++) {
            uint32_t a[4];
            a[0] = h2pack(accS[2 * kk][0],     accS[2 * kk][1]);
            a[1] = h2pack(accS[2 * kk][2],     accS[2 * kk][3]);
            a[2] = h2pack(accS[2 * kk + 1][0], accS[2 * kk + 1][1]);
            a[3] = h2pack(accS[2 * kk + 1][2], accS[2 * kk + 1][3]);
            #pragma unroll
            for (int p = 0; p < 2; p++) {
                uint32_t bb[4];
                ldsm4t(bb, smaddr(sVt) +
                           2 * ((kk * 16 + vrow) * 136 + h * HD + p * 16 + vcol));
                mma16(accO[task][2 * p],     a, bb);
                mma16(accO[task][2 * p + 1], a, bb + 2);
            }
        }
    }

    // ---- O tile (fp16) into sX ----
    #pragma unroll
    for (int task = 0; task < 2; task++) {
        const int rg = task * 8 + warp;
        const int h  = rg >> 2;
        const int mB = (rg & 3) * 16;
        #pragma unroll
        for (int nt = 0; nt < 4; nt++) {
            const int c2 = h * 16 + nt * 4 + tg;
            sX[(mB + g) * SH + c2]     = h2pack(accO[task][nt][0], accO[task][nt][1]);
            sX[(mB + 8 + g) * SH + c2] = h2pack(accO[task][nt][2], accO[task][nt][3]);
        }
    }
    __syncthreads();   // O complete + Wp copy complete

    // ---- out[64,128] = O @ Wp^T + bp ----
    const int wm = warp & 3;
    const int wn = warp >> 2;
    float acc2[8][4];
    #pragma unroll
    for (int nt = 0; nt < 8; nt++)
        #pragma unroll
        for (int j = 0; j < 4; j++) acc2[nt][j] = 0.f;

    const uint32_t aO = smaddr(sX) + 2 * (wm * 16 * 136 + laneA);
    uint32_t bO[4];
    #pragma unroll
    for (int p = 0; p < 4; p++)
        bO[p] = smaddr(sW) + 2 * ((wn * 64 + p * 16) * 136 + laneB);

    #pragma unroll
    for (int kk = 0; kk < 8; kk++) {
        uint32_t a[4];
        ldsm4(a, aO + kk * 32);
        #pragma unroll
        for (int p = 0; p < 4; p++) {
            uint32_t bb[4];
            ldsm4(bb, bO[p] + kk * 32);
            mma16(acc2[2 * p],     a, bb);
            mma16(acc2[2 * p + 1], a, bb + 2);
        }
    }

    const int r0 = wm * 16 + g, r1 = r0 + 8;
    #pragma unroll
    for (int nt = 0; nt < 8; nt++) {
        const int c = wn * 64 + nt * 8 + 2 * tg;
        const float b0 = bp[c], b1 = bp[c + 1];
        if (r0 < NTOK)
            *reinterpret_cast<float2*>(out + base + r0 * DIM + c) =
                make_float2(acc2[nt][0] + b0, acc2[nt][1] + b1);
        if (r1 < NTOK)
            *reinterpret_cast<float2*>(out + base + r1 * DIM + c) =
                make_float2(acc2[nt][2] + b0, acc2[nt][3] + b1);
    }
}

#define FUSED_SMEM ((4 * MPAD * SH + 128 * SH) * 4)   // 104448 B

extern "C" void kernel_launch(void* const* d_in, const int* in_sizes, int n_in,
                              void* d_out, int out_size)
{
    const float* query      = (const float*)d_in[0];
    const float* key        = (const float*)d_in[1];
    const float* value      = (const float*)d_in[2];
    const float* Wq         = (const float*)d_in[3];
    const float* bq         = (const float*)d_in[4];
    const float* Wk         = (const float*)d_in[5];
    const float* bk         = (const float*)d_in[6];
    const float* Wv         = (const float*)d_in[7];
    const float* bv         = (const float*)d_in[8];
    const float* bias_table = (const float*)d_in[9];
    const float* Wp         = (const float*)d_in[10];
    const float* bp         = (const float*)d_in[11];
    const float* mask       = (const float*)d_in[12];
    const int*   rel_index  = (const int*)d_in[13];
    float* out = (float*)d_out;

    cudaFuncSetAttribute(swin_kernel,
                         cudaFuncAttributeMaxDynamicSharedMemorySize, FUSED_SMEM);

    biasfrag_kernel<<<(NWIN * HEADS * 4 * 2 * 8 * 32) / 256, 256>>>(
        bias_table, rel_index, mask);
    w16_kernel<<<128, 256>>>(Wq, Wk, Wv, Wp);

    swin_kernel<<<NBLK, 256, FUSED_SMEM>>>(
        query, key, value, bq, bk, bv, bp, out);
}